// round 14
// baseline (speedup 1.0000x reference)
#include <cuda_runtime.h>

#define IN_C 32
#define OUT_C 64
#define HH 256
#define WW 256
#define NB 2
#define KTOT 864                 // 3 sets x 32 ch x 9 positions
#define KC 16                    // k-chunk
#define NCHUNK (KTOT / KC)       // 54
#define TPX 16                   // tile width (pixels)
#define TPY 8                    // tile height
#define NPIX 128                 // pixels per block tile
#define HALO_W 18
#define HALO_H 10
#define CPITCH (HALO_H * HALO_W) // 180 floats per channel

// Weights k-major, k = (t*9+p)*32 + c  -> g_W[k*64 + o]
__device__ __align__(16) float g_W[KTOT * OUT_C];

__global__ void setup_kernel(const float* __restrict__ w0,
                             const float* __restrict__ w1,
                             const float* __restrict__ w2) {
    int idx = blockIdx.x * blockDim.x + threadIdx.x;
    if (idx >= KTOT * OUT_C) return;
    int k = idx >> 6;
    int o = idx & 63;
    int tp = k >> 5;            // t*9+p
    int c  = k & 31;
    int t  = tp / 9;
    int p  = tp - t * 9;
    const float* w = (t == 0) ? w0 : (t == 1) ? w1 : w2;
    g_W[k * OUT_C + o] = w[o * (IN_C * 9) + c * 9 + p];
}

// 128 threads: 64 outch x 128 pixels (16x8 spatial). Micro-tile 8o x 8pix.
// Thread's o-channels: oa..oa+3 and oa+32..oa+35 (conflict-free As reads).
__global__ __launch_bounds__(128, 4)
void conv25d_kernel(const float* __restrict__ x,
                    const float* __restrict__ disp,
                    const float* __restrict__ fx,
                    const float* __restrict__ baseline,
                    float* __restrict__ out) {
    __shared__ float xs[IN_C * CPITCH];              // 23.0 KB
    __shared__ float dsh[CPITCH];                    // 0.72 KB
    __shared__ unsigned char mskb[27 * NPIX];        // 3.4 KB, [(t*9+p)][pix]
    __shared__ __align__(16) float As[KC * OUT_C];   // 4 KB
    __shared__ __align__(16) float Bs[KC * NPIX];    // 8 KB

    const int tid = threadIdx.x;
    const int n  = blockIdx.z;
    const int x0 = blockIdx.x * TPX;
    const int y0 = blockIdx.y * TPY;

    const float fxv = fx[n];
    const float bfx = __fmul_rn(baseline[n], fxv);

    // ---- load disp tile (10x18 halo, zero-padded OOB) ----
    const float* dbase = disp + (size_t)n * (HH * WW);
    for (int i = tid; i < CPITCH; i += 128) {
        int yy = i / HALO_W, xx = i - yy * HALO_W;
        int gy = y0 + yy - 1, gx = x0 + xx - 1;
        float v = 0.f;
        if (gy >= 0 && gy < HH && gx >= 0 && gx < WW) v = dbase[gy * WW + gx];
        dsh[i] = v;
    }
    // ---- load x tile (32 x 10 x 18) ----
    const float* xbase = x + (size_t)n * (IN_C * HH * WW);
    for (int i = tid; i < IN_C * CPITCH; i += 128) {
        int c = i / CPITCH; int rem = i - c * CPITCH;
        int yy = rem / HALO_W, xx = rem - yy * HALO_W;
        int gy = y0 + yy - 1, gx = x0 + xx - 1;
        float v = 0.f;
        if (gy >= 0 && gy < HH && gx >= 0 && gx < WW)
            v = xbase[(size_t)c * (HH * WW) + gy * WW + gx];
        xs[i] = v;
    }
    __syncthreads();

    // ---- masks (IEEE-RN, mirrors reference fp32 exactly); {0,1} as bytes ----
    for (int i = tid; i < NPIX * 9; i += 128) {
        int pix = i / 9, p = i - pix * 9;
        int ty = pix >> 4, tx = pix & 15;
        float dc = dsh[(ty + 1) * HALO_W + tx + 1];
        float vc = (dc != 0.f) ? 1.f : 0.f;
        float cd = __fdiv_rn(bfx, fminf(fmaxf(__fmul_rn(dc, vc), 0.01f), 256.f));
        float gr = __fdiv_rn(__fmul_rn(16.f, cd), fxv);
        float hf = 0.5f * gr;
        int dy = p / 3, dx = p - dy * 3;
        float d = dsh[(ty + dy) * HALO_W + tx + dx];
        float v = ((d != 0.f) ? 1.f : 0.f) * vc;
        float de = __fdiv_rn(bfx, fminf(fmaxf(__fmul_rn(d, v), 0.01f), 256.f));
        float m0 = (fabsf(de - (cd + gr)) <= hf) ? 1.f : 0.f;
        float m1 = (fabsf(de - cd)        <= hf) ? 1.f : 0.f;
        m1 = fminf(m1 + 1.f - v, 1.f);   // clip(m1 + 1 - valid, 0, 1)
        float m2 = (fabsf(de - (cd - gr)) <= hf) ? 1.f : 0.f;
        mskb[(0 * 9 + p) * NPIX + pix] = (unsigned char)m0;
        mskb[(1 * 9 + p) * NPIX + pix] = (unsigned char)m1;
        mskb[(2 * 9 + p) * NPIX + pix] = (unsigned char)m2;
    }

    // ---- GEMM mapping ----
    const int oa   = (tid & 7) * 4;        // o: oa..oa+3 and oa+32..oa+35
    const int pgrp = tid >> 3;             // 0..15
    const int pixb = pgrp * 8;             // 8 pixels

    // staging: thread owns pixel column tid
    const int pix_s = tid;
    const int sb = (tid >> 4) * HALO_W + (tid & 15);  // xs offset of pixel

    // A staging: As row = 16 float4; 8 threads/row x 2 float4
    const int aRow  = tid >> 3;            // 0..15
    const int aCol4 = (tid & 7) * 2;

    float4 aPre[2];
    {
        const float4* src = (const float4*)g_W + (size_t)aRow * 16 + aCol4;
        aPre[0] = src[0]; aPre[1] = src[1];
    }

    float acc[8][8];
    #pragma unroll
    for (int io = 0; io < 8; io++)
        #pragma unroll
        for (int ip = 0; ip < 8; ip++) acc[io][ip] = 0.f;

    __syncthreads();  // xs + mskb ready

    for (int ch = 0; ch < NCHUNK; ch++) {
        // store prefetched A chunk
        {
            float4* dst = (float4*)As + (size_t)aRow * 16 + aCol4;
            dst[0] = aPre[0]; dst[1] = aPre[1];
        }
        // stage B: chunk has fixed (t,p); c = c0..c0+15
        {
            int tp = ch >> 1;
            int c0 = (ch & 1) * KC;
            int t  = tp / 9;
            int p  = tp - t * 9;
            int dy = p / 3, dx = p - dy * 3;
            float mf = (float)mskb[tp * NPIX + pix_s];
            int base = c0 * CPITCH + dy * HALO_W + dx + sb;
            #pragma unroll
            for (int r = 0; r < KC; r++)
                Bs[r * NPIX + pix_s] = xs[base + r * CPITCH] * mf;
        }
        __syncthreads();

        // prefetch next A chunk (L2-resident)
        if (ch + 1 < NCHUNK) {
            const float4* src = (const float4*)g_W
                              + ((size_t)(ch + 1) * KC + aRow) * 16 + aCol4;
            aPre[0] = src[0]; aPre[1] = src[1];
        }

        // micro-GEMM: 16 k-steps x (8 o x 8 pix)
        #pragma unroll 4
        for (int kk = 0; kk < KC; kk++) {
            float4 a0 = *(const float4*)&As[kk * OUT_C + oa];
            float4 a1 = *(const float4*)&As[kk * OUT_C + oa + 32];
            float4 b0 = *(const float4*)&Bs[kk * NPIX + pixb];
            float4 b1 = *(const float4*)&Bs[kk * NPIX + pixb + 4];
            acc[0][0] += a0.x * b0.x; acc[0][1] += a0.x * b0.y;
            acc[0][2] += a0.x * b0.z; acc[0][3] += a0.x * b0.w;
            acc[0][4] += a0.x * b1.x; acc[0][5] += a0.x * b1.y;
            acc[0][6] += a0.x * b1.z; acc[0][7] += a0.x * b1.w;
            acc[1][0] += a0.y * b0.x; acc[1][1] += a0.y * b0.y;
            acc[1][2] += a0.y * b0.z; acc[1][3] += a0.y * b0.w;
            acc[1][4] += a0.y * b1.x; acc[1][5] += a0.y * b1.y;
            acc[1][6] += a0.y * b1.z; acc[1][7] += a0.y * b1.w;
            acc[2][0] += a0.z * b0.x; acc[2][1] += a0.z * b0.y;
            acc[2][2] += a0.z * b0.z; acc[2][3] += a0.z * b0.w;
            acc[2][4] += a0.z * b1.x; acc[2][5] += a0.z * b1.y;
            acc[2][6] += a0.z * b1.z; acc[2][7] += a0.z * b1.w;
            acc[3][0] += a0.w * b0.x; acc[3][1] += a0.w * b0.y;
            acc[3][2] += a0.w * b0.z; acc[3][3] += a0.w * b0.w;
            acc[3][4] += a0.w * b1.x; acc[3][5] += a0.w * b1.y;
            acc[3][6] += a0.w * b1.z; acc[3][7] += a0.w * b1.w;
            acc[4][0] += a1.x * b0.x; acc[4][1] += a1.x * b0.y;
            acc[4][2] += a1.x * b0.z; acc[4][3] += a1.x * b0.w;
            acc[4][4] += a1.x * b1.x; acc[4][5] += a1.x * b1.y;
            acc[4][6] += a1.x * b1.z; acc[4][7] += a1.x * b1.w;
            acc[5][0] += a1.y * b0.x; acc[5][1] += a1.y * b0.y;
            acc[5][2] += a1.y * b0.z; acc[5][3] += a1.y * b0.w;
            acc[5][4] += a1.y * b1.x; acc[5][5] += a1.y * b1.y;
            acc[5][6] += a1.y * b1.z; acc[5][7] += a1.y * b1.w;
            acc[6][0] += a1.z * b0.x; acc[6][1] += a1.z * b0.y;
            acc[6][2] += a1.z * b0.z; acc[6][3] += a1.z * b0.w;
            acc[6][4] += a1.z * b1.x; acc[6][5] += a1.z * b1.y;
            acc[6][6] += a1.z * b1.z; acc[6][7] += a1.z * b1.w;
            acc[7][0] += a1.w * b0.x; acc[7][1] += a1.w * b0.y;
            acc[7][2] += a1.w * b0.z; acc[7][3] += a1.w * b0.w;
            acc[7][4] += a1.w * b1.x; acc[7][5] += a1.w * b1.y;
            acc[7][6] += a1.w * b1.z; acc[7][7] += a1.w * b1.w;
        }
        __syncthreads();
    }

    // ---- epilogue: 8 o-rows x 8 consecutive x in one image row ----
    const int py  = pgrp >> 1;
    const int px0 = (pgrp & 1) * 8;
    const int gy  = y0 + py;
    float* obase = out + (size_t)n * OUT_C * HH * WW;
    #pragma unroll
    for (int io = 0; io < 8; io++) {
        int o = oa + ((io < 4) ? io : (28 + io));   // oa+io or oa+32+(io-4)
        float* po = obase + ((size_t)o * HH + gy) * WW + x0 + px0;
        *(float4*)po       = make_float4(acc[io][0], acc[io][1], acc[io][2], acc[io][3]);
        *(float4*)(po + 4) = make_float4(acc[io][4], acc[io][5], acc[io][6], acc[io][7]);
    }
}

extern "C" void kernel_launch(void* const* d_in, const int* in_sizes, int n_in,
                              void* d_out, int out_size) {
    const float* x    = (const float*)d_in[0];
    const float* disp = (const float*)d_in[1];
    const float* fx   = (const float*)d_in[2];
    const float* bl   = (const float*)d_in[3];
    const float* w0   = (const float*)d_in[4];
    const float* w1   = (const float*)d_in[5];
    const float* w2   = (const float*)d_in[6];

    setup_kernel<<<(KTOT * OUT_C + 255) / 256, 256>>>(w0, w1, w2);

    dim3 grid(WW / TPX, HH / TPY, NB);
    conv25d_kernel<<<grid, 128>>>(x, disp, fx, bl, (float*)d_out);
}

// round 17
// speedup vs baseline: 1.5586x; 1.5586x over previous
#include <cuda_runtime.h>
#include <cstdint>

#define IN_C 32
#define OUT_C 64
#define HH 256
#define WW 256
#define NB 2
#define KTOT 864                 // 3 sets x 32 ch x 9 positions
#define KC 16                    // k-chunk
#define NCHUNK (KTOT / KC)       // 54
#define TPX 16                   // tile width (pixels)
#define TPY 8                    // tile height
#define NPIX 128                 // pixels per block tile
#define HALO_W 18
#define HALO_H 10
#define CPITCH (HALO_H * HALO_W) // 180 floats per channel

// Weights k-major, k = (t*9+p)*32 + c  -> g_W[k*64 + o]
__device__ __align__(16) float g_W[KTOT * OUT_C];

__global__ void setup_kernel(const float* __restrict__ w0,
                             const float* __restrict__ w1,
                             const float* __restrict__ w2) {
    int idx = blockIdx.x * blockDim.x + threadIdx.x;
    if (idx >= KTOT * OUT_C) return;
    int k = idx >> 6;
    int o = idx & 63;
    int tp = k >> 5;            // t*9+p
    int c  = k & 31;
    int t  = tp / 9;
    int p  = tp - t * 9;
    const float* w = (t == 0) ? w0 : (t == 1) ? w1 : w2;
    g_W[k * OUT_C + o] = w[o * (IN_C * 9) + c * 9 + p];
}

__device__ __forceinline__ void cp_async16(uint32_t dst_smem, const void* src) {
    asm volatile("cp.async.ca.shared.global [%0], [%1], 16;"
                 :: "r"(dst_smem), "l"(src));
}
__device__ __forceinline__ void cp_commit() {
    asm volatile("cp.async.commit_group;");
}
__device__ __forceinline__ void cp_wait0() {
    asm volatile("cp.async.wait_group 0;" ::: "memory");
}

// 128 threads: 64 outch x 128 pixels (16x8 spatial). Micro-tile 8o x 8pix.
// Thread's o-channels: oa..oa+3 and oa+32..oa+35 (conflict-free As reads).
// A staged via cp.async into a double buffer (no register prefetch block).
__global__ __launch_bounds__(128, 4)
void conv25d_kernel(const float* __restrict__ x,
                    const float* __restrict__ disp,
                    const float* __restrict__ fx,
                    const float* __restrict__ baseline,
                    float* __restrict__ out) {
    __shared__ float xs[IN_C * CPITCH];              // 23.0 KB
    __shared__ float dsh[CPITCH];                    // 0.72 KB
    __shared__ unsigned char mskb[27 * NPIX];        // 3.4 KB, [(t*9+p)][pix]
    __shared__ __align__(16) float As2[2][KC * OUT_C]; // 8 KB (double buffer)
    __shared__ __align__(16) float Bs[KC * NPIX];    // 8 KB

    const int tid = threadIdx.x;
    const int n  = blockIdx.z;
    const int x0 = blockIdx.x * TPX;
    const int y0 = blockIdx.y * TPY;

    // A staging mapping: 16 rows x 16 float4; 8 threads/row x 2 float4
    const int aRow  = tid >> 3;            // 0..15
    const int aCol4 = (tid & 7) * 2;
    const float4* wsrc = (const float4*)g_W;
    uint32_t asBase0 = (uint32_t)__cvta_generic_to_shared(&As2[0][0]);
    uint32_t asOff   = (uint32_t)((aRow * 16 + aCol4) * 16); // bytes within buffer

    // prologue: async-stage chunk 0 into buffer 0 (overlaps halo/mask work)
    {
        const float4* src = wsrc + (size_t)aRow * 16 + aCol4;
        cp_async16(asBase0 + asOff,      src);
        cp_async16(asBase0 + asOff + 16, src + 1);
        cp_commit();
    }

    const float fxv = fx[n];
    const float bfx = __fmul_rn(baseline[n], fxv);

    // ---- load disp tile (10x18 halo, zero-padded OOB) ----
    const float* dbase = disp + (size_t)n * (HH * WW);
    for (int i = tid; i < CPITCH; i += 128) {
        int yy = i / HALO_W, xx = i - yy * HALO_W;
        int gy = y0 + yy - 1, gx = x0 + xx - 1;
        float v = 0.f;
        if (gy >= 0 && gy < HH && gx >= 0 && gx < WW) v = dbase[gy * WW + gx];
        dsh[i] = v;
    }
    // ---- load x tile (32 x 10 x 18) ----
    const float* xbase = x + (size_t)n * (IN_C * HH * WW);
    for (int i = tid; i < IN_C * CPITCH; i += 128) {
        int c = i / CPITCH; int rem = i - c * CPITCH;
        int yy = rem / HALO_W, xx = rem - yy * HALO_W;
        int gy = y0 + yy - 1, gx = x0 + xx - 1;
        float v = 0.f;
        if (gy >= 0 && gy < HH && gx >= 0 && gx < WW)
            v = xbase[(size_t)c * (HH * WW) + gy * WW + gx];
        xs[i] = v;
    }
    __syncthreads();

    // ---- masks (IEEE-RN, mirrors reference fp32 exactly); {0,1} as bytes ----
    for (int i = tid; i < NPIX * 9; i += 128) {
        int pix = i / 9, p = i - pix * 9;
        int ty = pix >> 4, tx = pix & 15;
        float dc = dsh[(ty + 1) * HALO_W + tx + 1];
        float vc = (dc != 0.f) ? 1.f : 0.f;
        float cd = __fdiv_rn(bfx, fminf(fmaxf(__fmul_rn(dc, vc), 0.01f), 256.f));
        float gr = __fdiv_rn(__fmul_rn(16.f, cd), fxv);
        float hf = 0.5f * gr;
        int dy = p / 3, dx = p - dy * 3;
        float d = dsh[(ty + dy) * HALO_W + tx + dx];
        float v = ((d != 0.f) ? 1.f : 0.f) * vc;
        float de = __fdiv_rn(bfx, fminf(fmaxf(__fmul_rn(d, v), 0.01f), 256.f));
        float m0 = (fabsf(de - (cd + gr)) <= hf) ? 1.f : 0.f;
        float m1 = (fabsf(de - cd)        <= hf) ? 1.f : 0.f;
        m1 = fminf(m1 + 1.f - v, 1.f);   // clip(m1 + 1 - valid, 0, 1)
        float m2 = (fabsf(de - (cd - gr)) <= hf) ? 1.f : 0.f;
        mskb[(0 * 9 + p) * NPIX + pix] = (unsigned char)m0;
        mskb[(1 * 9 + p) * NPIX + pix] = (unsigned char)m1;
        mskb[(2 * 9 + p) * NPIX + pix] = (unsigned char)m2;
    }

    // ---- GEMM mapping ----
    const int oa   = (tid & 7) * 4;        // o: oa..oa+3 and oa+32..oa+35
    const int pgrp = tid >> 3;             // 0..15
    const int pixb = pgrp * 8;             // 8 pixels

    // staging: thread owns pixel column tid
    const int pix_s = tid;
    const int sb = (tid >> 4) * HALO_W + (tid & 15);  // xs offset of pixel

    float acc[8][8];
    #pragma unroll
    for (int io = 0; io < 8; io++)
        #pragma unroll
        for (int ip = 0; ip < 8; ip++) acc[io][ip] = 0.f;

    __syncthreads();  // xs + mskb ready

    for (int ch = 0; ch < NCHUNK; ch++) {
        const int buf = ch & 1;
        const float* As = As2[buf];

        // stage B: chunk has fixed (t,p); c = c0..c0+15
        {
            int tp = ch >> 1;
            int c0 = (ch & 1) * KC;
            int t  = tp / 9;
            int p  = tp - t * 9;
            int dy = p / 3, dx = p - dy * 3;
            float mf = (float)mskb[tp * NPIX + pix_s];
            int base = c0 * CPITCH + dy * HALO_W + dx + sb;
            #pragma unroll
            for (int r = 0; r < KC; r++)
                Bs[r * NPIX + pix_s] = xs[base + r * CPITCH] * mf;
        }
        cp_wait0();          // A for this chunk has landed
        __syncthreads();     // Bs + As[buf] visible to all

        // async-stage next chunk's A into the other buffer
        // (safe: other buffer's readers finished before the ch-1 end barrier)
        if (ch + 1 < NCHUNK) {
            const float4* src = wsrc + ((size_t)(ch + 1) * KC + aRow) * 16 + aCol4;
            uint32_t dst = asBase0 + (uint32_t)(((buf ^ 1) * KC * OUT_C) * 4) + asOff;
            cp_async16(dst,      src);
            cp_async16(dst + 16, src + 1);
            cp_commit();
        }

        // micro-GEMM: 16 k-steps x (8 o x 8 pix)
        #pragma unroll 2
        for (int kk = 0; kk < KC; kk++) {
            float4 a0 = *(const float4*)&As[kk * OUT_C + oa];
            float4 a1 = *(const float4*)&As[kk * OUT_C + oa + 32];
            float4 b0 = *(const float4*)&Bs[kk * NPIX + pixb];
            float4 b1 = *(const float4*)&Bs[kk * NPIX + pixb + 4];
            acc[0][0] += a0.x * b0.x; acc[0][1] += a0.x * b0.y;
            acc[0][2] += a0.x * b0.z; acc[0][3] += a0.x * b0.w;
            acc[0][4] += a0.x * b1.x; acc[0][5] += a0.x * b1.y;
            acc[0][6] += a0.x * b1.z; acc[0][7] += a0.x * b1.w;
            acc[1][0] += a0.y * b0.x; acc[1][1] += a0.y * b0.y;
            acc[1][2] += a0.y * b0.z; acc[1][3] += a0.y * b0.w;
            acc[1][4] += a0.y * b1.x; acc[1][5] += a0.y * b1.y;
            acc[1][6] += a0.y * b1.z; acc[1][7] += a0.y * b1.w;
            acc[2][0] += a0.z * b0.x; acc[2][1] += a0.z * b0.y;
            acc[2][2] += a0.z * b0.z; acc[2][3] += a0.z * b0.w;
            acc[2][4] += a0.z * b1.x; acc[2][5] += a0.z * b1.y;
            acc[2][6] += a0.z * b1.z; acc[2][7] += a0.z * b1.w;
            acc[3][0] += a0.w * b0.x; acc[3][1] += a0.w * b0.y;
            acc[3][2] += a0.w * b0.z; acc[3][3] += a0.w * b0.w;
            acc[3][4] += a0.w * b1.x; acc[3][5] += a0.w * b1.y;
            acc[3][6] += a0.w * b1.z; acc[3][7] += a0.w * b1.w;
            acc[4][0] += a1.x * b0.x; acc[4][1] += a1.x * b0.y;
            acc[4][2] += a1.x * b0.z; acc[4][3] += a1.x * b0.w;
            acc[4][4] += a1.x * b1.x; acc[4][5] += a1.x * b1.y;
            acc[4][6] += a1.x * b1.z; acc[4][7] += a1.x * b1.w;
            acc[5][0] += a1.y * b0.x; acc[5][1] += a1.y * b0.y;
            acc[5][2] += a1.y * b0.z; acc[5][3] += a1.y * b0.w;
            acc[5][4] += a1.y * b1.x; acc[5][5] += a1.y * b1.y;
            acc[5][6] += a1.y * b1.z; acc[5][7] += a1.y * b1.w;
            acc[6][0] += a1.z * b0.x; acc[6][1] += a1.z * b0.y;
            acc[6][2] += a1.z * b0.z; acc[6][3] += a1.z * b0.w;
            acc[6][4] += a1.z * b1.x; acc[6][5] += a1.z * b1.y;
            acc[6][6] += a1.z * b1.z; acc[6][7] += a1.z * b1.w;
            acc[7][0] += a1.w * b0.x; acc[7][1] += a1.w * b0.y;
            acc[7][2] += a1.w * b0.z; acc[7][3] += a1.w * b0.w;
            acc[7][4] += a1.w * b1.x; acc[7][5] += a1.w * b1.y;
            acc[7][6] += a1.w * b1.z; acc[7][7] += a1.w * b1.w;
        }
        __syncthreads();
    }

    // ---- epilogue: 8 o-rows x 8 consecutive x in one image row ----
    const int py  = pgrp >> 1;
    const int px0 = (pgrp & 1) * 8;
    const int gy  = y0 + py;
    float* obase = out + (size_t)n * OUT_C * HH * WW;
    #pragma unroll
    for (int io = 0; io < 8; io++) {
        int o = oa + ((io < 4) ? io : (28 + io));   // oa+io or oa+32+(io-4)
        float* po = obase + ((size_t)o * HH + gy) * WW + x0 + px0;
        *(float4*)po       = make_float4(acc[io][0], acc[io][1], acc[io][2], acc[io][3]);
        *(float4*)(po + 4) = make_float4(acc[io][4], acc[io][5], acc[io][6], acc[io][7]);
    }
}

extern "C" void kernel_launch(void* const* d_in, const int* in_sizes, int n_in,
                              void* d_out, int out_size) {
    const float* x    = (const float*)d_in[0];
    const float* disp = (const float*)d_in[1];
    const float* fx   = (const float*)d_in[2];
    const float* bl   = (const float*)d_in[3];
    const float* w0   = (const float*)d_in[4];
    const float* w1   = (const float*)d_in[5];
    const float* w2   = (const float*)d_in[6];

    setup_kernel<<<(KTOT * OUT_C + 255) / 256, 256>>>(w0, w1, w2);

    dim3 grid(WW / TPX, HH / TPY, NB);
    conv25d_kernel<<<grid, 128>>>(x, disp, fx, bl, (float*)d_out);
}